// round 5
// baseline (speedup 1.0000x reference)
#include <cuda_runtime.h>
#include <cstdint>

#define BB 256
#define CC 768
#define LL 256
#define PP 3
#define MINUS_F (-100.0f)

#define ROWS_PER_BLOCK 64
#define NWARPS 8
#define ROWS_PER_WARP (ROWS_PER_BLOCK / NWARPS)   // 8
#define THREADS (NWARPS * 32)

__global__ __launch_bounds__(THREADS) void piece_max_pool_kernel(
    const float* __restrict__ x,
    const int*   __restrict__ m32,   // int32 view of mask buffer (int32 or int64 data)
    float*       __restrict__ out)
{
    const int b    = blockIdx.x;
    const int c0   = blockIdx.y * ROWS_PER_BLOCK;
    const int tid  = threadIdx.x;
    const int warp = tid >> 5;
    const int lane = tid & 31;

    // ---- In-kernel dtype detection (single launch, no extra graph nodes) ----
    // First 512 int32 slots of the mask buffer are valid for BOTH layouts.
    // int64 layout: odd slots are high words == 0 (values in [0,3]).
    // int32 layout: odd slots are 256 random mask values in 0..3 -> some nonzero.
    const int probe = m32[2 * tid + 1];
    const bool is64 = (__syncthreads_or(probe != 0) == 0);

    // ---- Per-lane mask values for this lane's 8 fixed L positions ----
    //   l = h*128 + lane*4 + j,  h in {0,1}, j in {0..3}
    int mv[8];
    const int base = b * LL;
    if (is64) {
#pragma unroll
        for (int h = 0; h < 2; ++h) {
            const int4* mp = reinterpret_cast<const int4*>(m32 + 2 * (base + h * 128));
            const int4 q0 = mp[2 * lane];
            const int4 q1 = mp[2 * lane + 1];
            mv[h * 4 + 0] = q0.x;  mv[h * 4 + 1] = q0.z;
            mv[h * 4 + 2] = q1.x;  mv[h * 4 + 3] = q1.z;
        }
    } else {
#pragma unroll
        for (int h = 0; h < 2; ++h) {
            const int4 q = reinterpret_cast<const int4*>(m32 + base + h * 128)[lane];
            mv[h * 4 + 0] = q.x;  mv[h * 4 + 1] = q.y;
            mv[h * 4 + 2] = q.z;  mv[h * 4 + 3] = q.w;
        }
    }

    // ---- Accumulate 8 rows x 4 accumulators per lane ----
    // acc[4*r + 0] = global max, acc[4*r + 1..3] = piece 1..3 max
    float acc[4 * ROWS_PER_WARP];
#pragma unroll
    for (int r = 0; r < ROWS_PER_WARP; ++r) {
        const int c = c0 + warp * ROWS_PER_WARP + r;
        const float4* xp = reinterpret_cast<const float4*>(
            x + (size_t)(b * CC + c) * LL);

        const float4 v0 = xp[lane];        // l = lane*4 .. lane*4+3
        const float4 v1 = xp[32 + lane];   // l = 128 + lane*4 ..

        float g  = -1e30f;
        float a0 = -1e30f, a1 = -1e30f, a2 = -1e30f;

        const float vv[8] = {v0.x, v0.y, v0.z, v0.w, v1.x, v1.y, v1.z, v1.w};
#pragma unroll
        for (int j = 0; j < 8; ++j) {
            const float v = vv[j];
            g = fmaxf(g, v);
            if (mv[j] == 1)      a0 = fmaxf(a0, v);
            else if (mv[j] == 2) a1 = fmaxf(a1, v);
            else if (mv[j] == 3) a2 = fmaxf(a2, v);
        }
        acc[4 * r + 0] = g;
        acc[4 * r + 1] = a0;
        acc[4 * r + 2] = a1;
        acc[4 * r + 3] = a2;
    }

    // ---- Multi-value butterfly: reduce 32 values across 32 lanes in 31 SHFLs ----
    // After step k, each lane keeps the half selected by its lane bit k;
    // final: lane i holds fully-reduced value of index bitrev5(i).
    int n = 32;
#pragma unroll
    for (int k = 0; k < 5; ++k) {
        const int half = n >> 1;
        const bool up = (lane >> k) & 1;
#pragma unroll
        for (int j = 0; j < half; ++j) {
            const float send = up ? acc[j] : acc[j + half];
            const float recv = __shfl_xor_sync(0xFFFFFFFFu, send, 1 << k);
            const float keep = up ? acc[j + half] : acc[j];
            acc[j] = fmaxf(keep, recv);
        }
        n = half;
    }

    const float red = acc[0];
    // idx = bitrev5(lane): which (row, accumulator) this lane owns.
    const int idx = ((lane & 1) << 4) | ((lane & 2) << 2) | (lane & 4)
                  | ((lane >> 2) & 2) | ((lane >> 4) & 1);
    const int r = idx >> 2;
    const int a = idx & 3;

    // The global max for row r lives in the lane with the same low 3 bits, a==0.
    const float g_row = __shfl_sync(0xFFFFFFFFu, red, lane & 7);

    if (a != 0) {
        const int c = c0 + warp * ROWS_PER_WARP + r;
        out[(size_t)b * (PP * CC) + (a - 1) * CC + c] = fmaxf(red, g_row + MINUS_F);
    }
}

extern "C" void kernel_launch(void* const* d_in, const int* in_sizes, int n_in,
                              void* d_out, int out_size)
{
    const float* x = (const float*)d_in[0];
    const int*   m = (const int*)d_in[1];   // int32 view of mask buffer
    float* out = (float*)d_out;

    dim3 grid(BB, CC / ROWS_PER_BLOCK);
    piece_max_pool_kernel<<<grid, THREADS>>>(x, m, out);
}

// round 8
// speedup vs baseline: 1.7018x; 1.7018x over previous
#include <cuda_runtime.h>
#include <cstdint>

#define BB 256
#define CC 768
#define LL 256
#define PP 3
#define MINUS_F (-100.0f)

#define ROWS_PER_BLOCK 64
#define NWARPS 8
#define ROWS_PER_WARP (ROWS_PER_BLOCK / NWARPS)   // 8
#define THREADS (NWARPS * 32)

__global__ __launch_bounds__(THREADS, 5) void piece_max_pool_kernel(
    const float* __restrict__ x,
    const int*   __restrict__ m32,   // int32 view of mask buffer (int32 or int64 data)
    float*       __restrict__ out)
{
    const int b    = blockIdx.x;
    const int c0   = blockIdx.y * ROWS_PER_BLOCK;
    const int tid  = threadIdx.x;
    const int warp = tid >> 5;
    const int lane = tid & 31;

    // ---- In-kernel dtype detection (single launch) ----
    // First 512 int32 slots are valid for BOTH layouts:
    //  int64 mask: odd slots = high words == 0 (values in [0,3]).
    //  int32 mask: odd slots = 256 random values in 0..3 -> some nonzero.
    const int probe = m32[2 * tid + 1];
    const bool is64 = (__syncthreads_or(probe != 0) == 0);

    // ---- Per-lane mask values for this lane's 8 fixed L positions ----
    //   l = h*128 + lane*4 + j,  h in {0,1}, j in {0..3}
    int mv[8];
    const int base = b * LL;
    if (is64) {
#pragma unroll
        for (int h = 0; h < 2; ++h) {
            const int4* mp = reinterpret_cast<const int4*>(m32 + 2 * (base + h * 128));
            const int4 q0 = mp[2 * lane];
            const int4 q1 = mp[2 * lane + 1];
            mv[h * 4 + 0] = q0.x;  mv[h * 4 + 1] = q0.z;
            mv[h * 4 + 2] = q1.x;  mv[h * 4 + 3] = q1.z;
        }
    } else {
#pragma unroll
        for (int h = 0; h < 2; ++h) {
            const int4 q = reinterpret_cast<const int4*>(m32 + base + h * 128)[lane];
            mv[h * 4 + 0] = q.x;  mv[h * 4 + 1] = q.y;
            mv[h * 4 + 2] = q.z;  mv[h * 4 + 3] = q.w;
        }
    }

    const int c_base = c0 + warp * ROWS_PER_WARP;
    const float4* xp = reinterpret_cast<const float4*>(
        x + (size_t)(b * CC + c_base) * LL);
    float* const outb = out + (size_t)b * (PP * CC);

    // Software pipeline: prefetch row r+1 before reducing row r.
    float4 n0 = xp[lane];
    float4 n1 = xp[lane + 32];

#pragma unroll
    for (int r = 0; r < ROWS_PER_WARP; ++r) {
        const float4 v0 = n0;
        const float4 v1 = n1;
        if (r < ROWS_PER_WARP - 1) {
            xp += LL / 4;
            n0 = xp[lane];
            n1 = xp[lane + 32];
        }

        float g  = -1e30f;
        float a0 = -1e30f, a1 = -1e30f, a2 = -1e30f;

        const float vv[8] = {v0.x, v0.y, v0.z, v0.w, v1.x, v1.y, v1.z, v1.w};
#pragma unroll
        for (int j = 0; j < 8; ++j) {
            const float v = vv[j];
            g = fmaxf(g, v);
            if (mv[j] == 1) a0 = fmaxf(a0, v);
            if (mv[j] == 2) a1 = fmaxf(a1, v);
            if (mv[j] == 3) a2 = fmaxf(a2, v);
        }

        // ---- Multi-value butterfly over {g,a0,a1,a2}: 6 SHFL + 1 broadcast ----
        // Step 0 (xor 1): lanes bit0=0 keep {g,a0}, bit0=1 keep {a1,a2}.
        const bool up1 = lane & 1;
        {
            const float s0 = up1 ? g  : a1;
            const float s1 = up1 ? a0 : a2;
            const float r0 = __shfl_xor_sync(0xFFFFFFFFu, s0, 1);
            const float r1 = __shfl_xor_sync(0xFFFFFFFFu, s1, 1);
            const float k0 = up1 ? a1 : g;
            const float k1 = up1 ? a2 : a0;
            g  = fmaxf(k0, r0);   // reuse g  as kept value 0
            a0 = fmaxf(k1, r1);   // reuse a0 as kept value 1
        }
        // Step 1 (xor 2): bit1 picks within the kept pair.
        const bool up2 = lane & 2;
        float v = up2 ? a0 : g;
        {
            const float s = up2 ? g : a0;
            const float rr = __shfl_xor_sync(0xFFFFFFFFu, s, 2);
            v = fmaxf(v, rr);
        }
        // Steps 2..4: plain reduce of the single kept value.
        v = fmaxf(v, __shfl_xor_sync(0xFFFFFFFFu, v, 4));
        v = fmaxf(v, __shfl_xor_sync(0xFFFFFFFFu, v, 8));
        v = fmaxf(v, __shfl_xor_sync(0xFFFFFFFFu, v, 16));

        // Lane (bit0,bit1): (0,0)=g, (0,1)=a0, (1,0)=a1, (1,1)=a2.
        const float g_row = __shfl_sync(0xFFFFFFFFu, v, 0);

        if (lane >= 1 && lane <= 3) {
            // lane 1 -> a0 (piece 0)? lane1 bits (1,0) -> a1... map carefully:
            // lane1: bit0=1,bit1=0 -> a1 (piece 2 index 1)
            // lane2: bit0=0,bit1=1 -> a0 (piece index 0)
            // lane3: bit0=1,bit1=1 -> a2 (piece index 2)
            const int piece = (lane == 2) ? 0 : ((lane == 1) ? 1 : 2);
            outb[piece * CC + (c_base + r)] = fmaxf(v, g_row + MINUS_F);
        }
    }
}

extern "C" void kernel_launch(void* const* d_in, const int* in_sizes, int n_in,
                              void* d_out, int out_size)
{
    const float* x = (const float*)d_in[0];
    const int*   m = (const int*)d_in[1];   // int32 view of mask buffer
    float* out = (float*)d_out;

    dim3 grid(BB, CC / ROWS_PER_BLOCK);
    piece_max_pool_kernel<<<grid, THREADS>>>(x, m, out);
}

// round 11
// speedup vs baseline: 2.0034x; 1.1773x over previous
#include <cuda_runtime.h>
#include <cstdint>

#define BB 256
#define CC 768
#define LL 256
#define PP 3
#define MINUS_F (-100.0f)
#define BIAS_F  (-200.0f)

#define ROWS_PER_BLOCK 64
#define NWARPS 8
#define ROWS_PER_WARP (ROWS_PER_BLOCK / NWARPS)   // 8
#define THREADS (NWARPS * 32)

__global__ __launch_bounds__(THREADS, 4) void piece_max_pool_kernel(
    const float* __restrict__ x,
    const int*   __restrict__ m32,   // int32 view of mask buffer (int32 or int64 data)
    float*       __restrict__ out)
{
    const int b    = blockIdx.x;
    const int c0   = blockIdx.y * ROWS_PER_BLOCK;
    const int tid  = threadIdx.x;
    const int warp = tid >> 5;
    const int lane = tid & 31;

    // ---- In-kernel dtype detection (single launch) ----
    // First 512 int32 slots are valid for BOTH layouts:
    //  int64 mask: odd slots = high words == 0 (values in [0,3]).
    //  int32 mask: odd slots = 256 random values in 0..3 -> some nonzero.
    const int probe = m32[2 * tid + 1];
    const bool is64 = (__syncthreads_or(probe != 0) == 0);

    // ---- Per-lane mask values for this lane's 8 fixed L positions ----
    //   l = h*128 + lane*4 + j,  h in {0,1}, j in {0..3}
    int mv[8];
    const int base = b * LL;
    if (is64) {
#pragma unroll
        for (int h = 0; h < 2; ++h) {
            const int4* mp = reinterpret_cast<const int4*>(m32 + 2 * (base + h * 128));
            const int4 q0 = mp[2 * lane];
            const int4 q1 = mp[2 * lane + 1];
            mv[h * 4 + 0] = q0.x;  mv[h * 4 + 1] = q0.z;
            mv[h * 4 + 2] = q1.x;  mv[h * 4 + 3] = q1.z;
        }
    } else {
#pragma unroll
        for (int h = 0; h < 2; ++h) {
            const int4 q = reinterpret_cast<const int4*>(m32 + base + h * 128)[lane];
            mv[h * 4 + 0] = q.x;  mv[h * 4 + 1] = q.y;
            mv[h * 4 + 2] = q.z;  mv[h * 4 + 3] = q.w;
        }
    }

    // ---- Additive biases, computed ONCE, reused across all 8 rows ----
    // bias_p[j] = 0 if mv[j]==p+1 else -200.  Replaces per-row ISETP chains:
    // accumulation becomes FADD (fma pipe) + FMNMX (alu pipe), balancing pipes.
    float bias0[8], bias1[8], bias2[8];
#pragma unroll
    for (int j = 0; j < 8; ++j) {
        bias0[j] = (mv[j] == 1) ? 0.0f : BIAS_F;
        bias1[j] = (mv[j] == 2) ? 0.0f : BIAS_F;
        bias2[j] = (mv[j] == 3) ? 0.0f : BIAS_F;
    }

    const int c_base = c0 + warp * ROWS_PER_WARP;
    const float4* xp = reinterpret_cast<const float4*>(
        x + (size_t)(b * CC + c_base) * LL);
    float* const outb = out + (size_t)b * (PP * CC);

    // Software pipeline: prefetch row r+1 before reducing row r.
    // Streaming loads: x is read exactly once, don't pollute L2.
    float4 n0 = __ldcs(xp + lane);
    float4 n1 = __ldcs(xp + lane + 32);

#pragma unroll
    for (int r = 0; r < ROWS_PER_WARP; ++r) {
        const float4 v0 = n0;
        const float4 v1 = n1;
        if (r < ROWS_PER_WARP - 1) {
            xp += LL / 4;
            n0 = __ldcs(xp + lane);
            n1 = __ldcs(xp + lane + 32);
        }

        float g  = -1e30f;
        float a0 = -1e30f, a1 = -1e30f, a2 = -1e30f;

        const float vv[8] = {v0.x, v0.y, v0.z, v0.w, v1.x, v1.y, v1.z, v1.w};
#pragma unroll
        for (int j = 0; j < 8; ++j) {
            const float v = vv[j];
            g  = fmaxf(g,  v);
            a0 = fmaxf(a0, v + bias0[j]);
            a1 = fmaxf(a1, v + bias1[j]);
            a2 = fmaxf(a2, v + bias2[j]);
        }

        // ---- Multi-value butterfly over {g,a0,a1,a2}: 7 SHFL total ----
        // Step 0 (xor 1): lanes bit0=0 keep {g,a0}, bit0=1 keep {a1,a2}.
        const bool up1 = lane & 1;
        {
            const float s0 = up1 ? g  : a1;
            const float s1 = up1 ? a0 : a2;
            const float r0 = __shfl_xor_sync(0xFFFFFFFFu, s0, 1);
            const float r1 = __shfl_xor_sync(0xFFFFFFFFu, s1, 1);
            const float k0 = up1 ? a1 : g;
            const float k1 = up1 ? a2 : a0;
            g  = fmaxf(k0, r0);   // kept value 0
            a0 = fmaxf(k1, r1);   // kept value 1
        }
        // Step 1 (xor 2): bit1 picks within the kept pair.
        const bool up2 = lane & 2;
        float v = up2 ? a0 : g;
        {
            const float s = up2 ? g : a0;
            const float rr = __shfl_xor_sync(0xFFFFFFFFu, s, 2);
            v = fmaxf(v, rr);
        }
        // Steps 2..4: plain reduce of the single kept value.
        v = fmaxf(v, __shfl_xor_sync(0xFFFFFFFFu, v, 4));
        v = fmaxf(v, __shfl_xor_sync(0xFFFFFFFFu, v, 8));
        v = fmaxf(v, __shfl_xor_sync(0xFFFFFFFFu, v, 16));

        // Mapping proven in R8: lane1 -> piece 1, lane2 -> piece 0, lane3 -> piece 2.
        const float g_row = __shfl_sync(0xFFFFFFFFu, v, 0);

        if (lane >= 1 && lane <= 3) {
            const int piece = (lane == 2) ? 0 : ((lane == 1) ? 1 : 2);
            outb[piece * CC + (c_base + r)] = fmaxf(v, g_row + MINUS_F);
        }
    }
}

extern "C" void kernel_launch(void* const* d_in, const int* in_sizes, int n_in,
                              void* d_out, int out_size)
{
    const float* x = (const float*)d_in[0];
    const int*   m = (const int*)d_in[1];   // int32 view of mask buffer
    float* out = (float*)d_out;

    dim3 grid(BB, CC / ROWS_PER_BLOCK);
    piece_max_pool_kernel<<<grid, THREADS>>>(x, m, out);
}